// round 14
// baseline (speedup 1.0000x reference)
#include <cuda_runtime.h>

// ---------------- problem constants ----------------
#define KB     8
#define KC     64
#define KHW    76800      // 240*320
#define KCL    10
#define ALPHA_C   0.02f
#define DELTA_C   0.5f
#define MINW_C    50.0f

// persistent grid: 4 blocks/SM on 148 SMs (also fits 152-SM GB300)
#define GRID   592
#define THR    256

// phase-1 items: (b, 1280px chunk, channel-group), batch-major -> 960
#define CH1    60
#define PX1    (KHW / CH1)        // 1280
#define NIT1   (KB * CH1 * 2)     // 960
#define IT1PB  (CH1 * 2)          // 120 items per batch

// phase-2 items: (b, 512px chunk) -> 1200, processed by 1184 half-units
#define CH2    150
#define PX2    (KHW / CH2)        // 512
#define NIT2   (KB * CH2)         // 1200
#define NUNITS (GRID * 2)         // 1184

// ---------------- device scratch (zero-init .bss; kernel restores) --------
__device__ float g_sums[KB][KC][KCL];
__device__ float g_cnt[KB][KCL];
__device__ float g_means[KB][KCL][KC];
__device__ float g_inter;
__device__ float g_d2[KB * KCL];
__device__ float g_nk[KB * KCL];
__device__ unsigned int g_q1;        // phase-1 work queue
__device__ unsigned int g_t1[KB];    // per-batch phase-1 done tickets
__device__ unsigned int g_go[KB];    // per-batch means-ready flags
__device__ unsigned int g_q2;        // phase-2 work queue
__device__ unsigned int g_t3;        // phase-2 done ticket (half-units)

#define HBAR(h) asm volatile("bar.sync %0, 128;" :: "r"(1 + (h)) : "memory")

__global__ __launch_bounds__(THR, 4) void fused_loss(const float* __restrict__ x,
                                                     const int* __restrict__ cmask,
                                                     float* __restrict__ out)
{
    // float4 bins: bins[warp][k*32 + lane]; bank = (4*lane+j)%32, k-independent
    __shared__ float4 s_bins[8][KCL * 32];       // 40960 B (bins / means / msh)
    __shared__ unsigned char s_cm[PX1];
    __shared__ int s_cnt[KCL];
    __shared__ int s_item;
    __shared__ float s_r[8];
    __shared__ unsigned int s_flag;
    __shared__ int s_item2[2];
    __shared__ int s_fin[2];
    __shared__ float s_d2[2][KCL], s_nk[2][KCL];
    __shared__ float s_r1[2][4], s_r2[2][4];

    const int tid  = threadIdx.x;
    const int lane = tid & 31;
    const int warp = tid >> 5;
    float4* wacc4 = s_bins[warp];

    // ======================= PHASE 1: cluster sums =======================
    for (;;) {
        if (tid == 0) s_item = (int)atomicAdd(&g_q1, 1u);
        __syncthreads();
        const int item = s_item;
        if (item >= NIT1) break;

        const int b     = item / IT1PB;
        const int r0    = item % IT1PB;
        const int cgrp  = r0 & 1;
        const int pbase = (r0 >> 1) * PX1;

        // zero this warp's bins (warp-private, lane-column-private)
#pragma unroll
        for (int i = 0; i < KCL; i++)
            wacc4[i * 32 + lane] = make_float4(0.f, 0.f, 0.f, 0.f);
        if (tid < KCL) s_cnt[tid] = 0;

        // stage masks (+ counts only from channel-group 0)
        const int* cmb = cmask + b * KHW + pbase;
        if (cgrp == 0) {
            int cnt[KCL];
#pragma unroll
            for (int k = 0; k < KCL; k++) cnt[k] = 0;
#pragma unroll
            for (int i = 0; i < PX1 / 256; i++) {
                const int p = tid + i * 256;
                const int v = cmb[p];
                s_cm[p] = (unsigned char)v;
#pragma unroll
                for (int k = 0; k < KCL; k++) cnt[k] += (v == k);
            }
            __syncthreads();
#pragma unroll
            for (int k = 0; k < KCL; k++) {
                int v = cnt[k];
#pragma unroll
                for (int o = 16; o; o >>= 1) v += __shfl_xor_sync(0xffffffffu, v, o);
                if (lane == 0) atomicAdd(&s_cnt[k], v);
            }
            __syncthreads();
            if (tid < KCL) atomicAdd(&g_cnt[b][tid], (float)s_cnt[tid]);
        } else {
#pragma unroll
            for (int i = 0; i < PX1 / 256; i++) {
                const int p = tid + i * 256;
                s_cm[p] = (unsigned char)cmb[p];
            }
            __syncthreads();
        }

        // main accumulation: warp owns 4 channels; software-pipelined quads.
        // c0v..c3v = channel vectors over the quad's 4 pixels (.x=px0 .. .w=px3)
        const int c0 = cgrp * 32 + warp * 4;
        const float* xp = x + ((size_t)(b * KC + c0)) * KHW + pbase;

#define LOADQ(d0, d1, d2, d3, P)                                   \
        d0 = *(const float4*)(xp + (P));                           \
        d1 = *(const float4*)(xp + (size_t)KHW + (P));             \
        d2 = *(const float4*)(xp + (size_t)2 * KHW + (P));         \
        d3 = *(const float4*)(xp + (size_t)3 * KHW + (P))

        float4 c0v, c1v, c2v, c3v;
        unsigned int cmq;
        {
            const int p = 4 * lane;
            LOADQ(c0v, c1v, c2v, c3v, p);
            cmq = *(const unsigned int*)(s_cm + p);
        }

#pragma unroll
        for (int it = 0; it < PX1 / 128; it++) {
            float4 n0, n1, n2, n3;
            unsigned int cmn = 0;
            if (it + 1 < PX1 / 128) {
                const int pn = 4 * lane + (it + 1) * 128;
                LOADQ(n0, n1, n2, n3, pn);           // burst for it+1
                cmn = *(const unsigned int*)(s_cm + pn);
            }

            // ---- duplicate-resolved scatter ----
            const int k0 = cmq & 0xffu;
            const int k1 = (cmq >> 8) & 0xffu;
            const int k2 = (cmq >> 16) & 0xffu;
            const int k3 = cmq >> 24;

            // merge duplicate pixels into the earliest slot (branch-free)
            if (k1 == k0) { c0v.x += c0v.y; c1v.x += c1v.y; c2v.x += c2v.y; c3v.x += c3v.y; }
            if (k2 == k0) { c0v.x += c0v.z; c1v.x += c1v.z; c2v.x += c2v.z; c3v.x += c3v.z; }
            else if (k2 == k1) { c0v.y += c0v.z; c1v.y += c1v.z; c2v.y += c2v.z; c3v.y += c3v.z; }
            if (k3 == k0) { c0v.x += c0v.w; c1v.x += c1v.w; c2v.x += c2v.w; c3v.x += c3v.w; }
            else if (k3 == k1) { c0v.y += c0v.w; c1v.y += c1v.w; c2v.y += c2v.w; c3v.y += c3v.w; }
            else if (k3 == k2) { c0v.z += c0v.w; c1v.z += c1v.w; c2v.z += c2v.w; c3v.z += c3v.w; }
            const bool d1 = (k1 == k0);
            const bool d2 = (k2 == k0) | (k2 == k1);
            const bool d3 = (k3 == k0) | (k3 == k1) | (k3 == k2);

            // batched loads (loads commute; results pipeline -> ONE stall window)
            const float4 l0 = wacc4[k0 * 32 + lane];
            const float4 l1 = wacc4[k1 * 32 + lane];
            const float4 l2 = wacc4[k2 * 32 + lane];
            const float4 l3 = wacc4[k3 * 32 + lane];

            // stores: active slots have provably distinct addresses
            wacc4[k0 * 32 + lane] =
                make_float4(l0.x + c0v.x, l0.y + c1v.x, l0.z + c2v.x, l0.w + c3v.x);
            if (!d1) wacc4[k1 * 32 + lane] =
                make_float4(l1.x + c0v.y, l1.y + c1v.y, l1.z + c2v.y, l1.w + c3v.y);
            if (!d2) wacc4[k2 * 32 + lane] =
                make_float4(l2.x + c0v.z, l2.y + c1v.z, l2.z + c2v.z, l2.w + c3v.z);
            if (!d3) wacc4[k3 * 32 + lane] =
                make_float4(l3.x + c0v.w, l3.y + c1v.w, l3.z + c2v.w, l3.w + c3v.w);

            c0v = n0; c1v = n1; c2v = n2; c3v = n3; cmq = cmn;
        }
#undef LOADQ

        // per-warp bin reduce -> global atomics (10 float4 rows)
#pragma unroll
        for (int r = 0; r < KCL; r++) {
            float4 v = wacc4[r * 32 + lane];
#pragma unroll
            for (int o = 16; o; o >>= 1) {
                v.x += __shfl_xor_sync(0xffffffffu, v.x, o);
                v.y += __shfl_xor_sync(0xffffffffu, v.y, o);
                v.z += __shfl_xor_sync(0xffffffffu, v.z, o);
                v.w += __shfl_xor_sync(0xffffffffu, v.w, o);
            }
            if (lane == 0) {
                atomicAdd(&g_sums[b][c0 + 0][r], v.x);
                atomicAdd(&g_sums[b][c0 + 1][r], v.y);
                atomicAdd(&g_sums[b][c0 + 2][r], v.z);
                atomicAdd(&g_sums[b][c0 + 3][r], v.w);
            }
        }

        // ---- per-batch ticket: 120th finisher computes batch-b means ----
        __threadfence();
        __syncthreads();
        if (tid == 0)
            s_flag = (atomicAdd(&g_t1[b], 1u) == IT1PB - 1) ? 1u : 0u;
        __syncthreads();

        if (s_flag) {
            __threadfence();
            float* s_means = (float*)&s_bins[0][0];   // bins dead; 10x65 staging
            for (int row = warp; row < KCL; row += 8) {
                const float cntv = g_cnt[b][row];
                const float m0 = g_sums[b][lane][row]      / (cntv + 1e-10f);
                const float m1 = g_sums[b][lane + 32][row] / (cntv + 1e-10f);
                float sq = m0 * m0 + m1 * m1;
#pragma unroll
                for (int o = 16; o; o >>= 1) sq += __shfl_xor_sync(0xffffffffu, sq, o);
                const float inv = 1.0f / fmaxf(sqrtf(sq), 1e-12f);
                const float n0 = m0 * inv, n1 = m1 * inv;
                g_means[b][row][lane]      = n0;
                g_means[b][row][lane + 32] = n1;
                s_means[row * 65 + lane]      = n0;
                s_means[row * 65 + lane + 32] = n1;
                g_sums[b][lane][row]      = 0.0f;     // reset for next replay
                g_sums[b][lane + 32][row] = 0.0f;
                if (lane == 0) g_cnt[b][row] = 0.0f;
            }
            __syncthreads();

            // inter loss for batch b: 90 ordered pairs / 8 warps
            float acc_inter = 0.f;
            for (int pr = warp; pr < KCL * (KCL - 1); pr += 8) {
                const int k = pr / 9;
                int l = pr % 9; if (l >= k) l++;
                const float* mk = &s_means[k * 65];
                const float* ml = &s_means[l * 65];
                float dv = mk[lane] * ml[lane] + mk[lane + 32] * ml[lane + 32];
#pragma unroll
                for (int o = 16; o; o >>= 1) dv += __shfl_xor_sync(0xffffffffu, dv, o);
                const float h = fmaxf(DELTA_C - 0.5f * (1.0f - dv), 0.0f);
                if (lane == 0) acc_inter += h * h;
            }
            if (lane == 0) s_r[warp] = acc_inter;
            __syncthreads();
            if (tid == 0) {
                float t = 0.f;
#pragma unroll
                for (int w = 0; w < 8; w++) t += s_r[w];
                atomicAdd(&g_inter, t);
                __threadfence();
                atomicExch(&g_go[b], 1u);     // release batch b
            }
            __syncthreads();
        }
    }

    // ======================= PHASE 2: intra pass ==========================
    // two independent 128-thread half-units per block; REVERSE batch order
    const int half = warp >> 2;
    const int htid = tid & 127;
    const int hwarp = warp & 3;
    float* msh = (float*)&s_bins[0][0] + half * 704;
    int curb = -1;

    for (;;) {
        if (htid == 0) s_item2[half] = (int)atomicAdd(&g_q2, 1u);
        HBAR(half);
        const int it2 = s_item2[half];
        if (it2 >= NIT2) break;
        const int rit   = (NIT2 - 1) - it2;       // reversed traversal
        const int b     = rit / CH2;
        const int pbase = (rit % CH2) * PX2;

        if (htid == 0) {
            while (atomicAdd(&g_go[b], 0u) == 0u) __nanosleep(64);
        }
        HBAR(half);
        __threadfence();                           // acquire g_means[b]

        if (b != curb) {
            for (int i = htid; i < KCL * KC; i += 128)
                msh[(i >> 6) * 65 + (i & 63)] = ((const float*)g_means)[b * KCL * KC + i];
            curb = b;
        }
        if (htid < KCL) { s_d2[half][htid] = 0.f; s_nk[half][htid] = 0.f; }
        HBAR(half);

        const int p0 = pbase + htid * 4;
        const int4 cm4 = *(const int4*)(cmask + b * KHW + p0);
        const float* xb = x + (size_t)b * KC * KHW + p0;

        const int kk4[4] = { cm4.x, cm4.y, cm4.z, cm4.w };
        const float* mp0 = &msh[cm4.x * 65];
        const float* mp1 = &msh[cm4.y * 65];
        const float* mp2 = &msh[cm4.z * 65];
        const float* mp3 = &msh[cm4.w * 65];

        float d0 = 0.f, d1 = 0.f, d2 = 0.f, d3 = 0.f;
#pragma unroll
        for (int w = 0; w < KC / 8; w++) {
            float4 buf[8];
#pragma unroll
            for (int cc = 0; cc < 8; cc++)
                buf[cc] = *(const float4*)(xb + (size_t)(w * 8 + cc) * KHW);
#pragma unroll
            for (int cc = 0; cc < 8; cc++) {
                const int c = w * 8 + cc;
                d0 = fmaf(buf[cc].x, mp0[c], d0);
                d1 = fmaf(buf[cc].y, mp1[c], d1);
                d2 = fmaf(buf[cc].z, mp2[c], d2);
                d3 = fmaf(buf[cc].w, mp3[c], d3);
            }
        }

        const float dots[4] = { d0, d1, d2, d3 };
#pragma unroll
        for (int i = 0; i < 4; i++) {
            const float dd = 0.5f * (1.0f - dots[i]);
            atomicAdd(&s_d2[half][kk4[i]], dd * dd);
            if (dd > ALPHA_C) atomicAdd(&s_nk[half][kk4[i]], 1.0f);
        }
        HBAR(half);
        if (htid < KCL) {
            atomicAdd(&g_d2[b * KCL + htid], s_d2[half][htid]);
            atomicAdd(&g_nk[b * KCL + htid], s_nk[half][htid]);
        }
    }

    // ---- phase-2 ticket: last half-unit finalizes + resets everything ----
    __threadfence();
    if (htid == 0) s_fin[half] = (atomicAdd(&g_t3, 1u) == NUNITS - 1) ? 1 : 0;
    HBAR(half);
    if (!s_fin[half]) return;
    __threadfence();

    float acc_intra = 0.f, acc_ind = 0.f;
    if (htid < KB * KCL) {
        const float nk = g_nk[htid];
        acc_intra = g_d2[htid] / (fmaxf(nk, MINW_C) * (float)KCL);
        acc_ind   = nk;
        g_nk[htid] = 0.f;
        g_d2[htid] = 0.f;
    }
    float v1 = acc_intra, v2 = acc_ind;
#pragma unroll
    for (int o = 16; o; o >>= 1) {
        v1 += __shfl_xor_sync(0xffffffffu, v1, o);
        v2 += __shfl_xor_sync(0xffffffffu, v2, o);
    }
    if (lane == 0) { s_r1[half][hwarp] = v1; s_r2[half][hwarp] = v2; }
    HBAR(half);
    if (htid == 0) {
        float t1 = 0.f, t2 = 0.f;
#pragma unroll
        for (int w = 0; w < 4; w++) { t1 += s_r1[half][w]; t2 += s_r2[half][w]; }
        const float inter_loss = g_inter / ((float)(KCL * (KCL - 1) / 2) * (float)KB);
        const float intra_loss = (t2 > 0.f) ? (t1 / (float)KB) : 0.f;
        out[0] = intra_loss + inter_loss;
        out[1] = intra_loss;
        out[2] = inter_loss;
        // reset control state for the next graph replay
        g_q1 = 0u; g_q2 = 0u; g_t3 = 0u; g_inter = 0.f;
    }
    if (htid < KB) { g_t1[htid] = 0u; g_go[htid] = 0u; }
}

// =====================================================================
extern "C" void kernel_launch(void* const* d_in, const int* in_sizes, int n_in,
                              void* d_out, int out_size)
{
    const float* x   = (const float*)d_in[0];
    const int*   cm  = (const int*)d_in[1];
    float*       out = (float*)d_out;

    fused_loss<<<GRID, THR>>>(x, cm, out);
}

// round 16
// speedup vs baseline: 1.0520x; 1.0520x over previous
#include <cuda_runtime.h>

// ---------------- problem constants ----------------
#define KB     8
#define KC     64
#define KHW    76800      // 240*320
#define KCL    10
#define ALPHA_C   0.02f
#define DELTA_C   0.5f
#define MINW_C    50.0f

// persistent grid: 4 blocks/SM on 148 SMs (also fits 152-SM GB300)
#define GRID   592
#define THR    256

// phase-1 items: (b, 1280px chunk, channel-group), batch-major -> 960
#define CH1    60
#define PX1    (KHW / CH1)        // 1280
#define NIT1   (KB * CH1 * 2)     // 960
#define IT1PB  (CH1 * 2)          // 120 items per batch

// phase-2 items: (b, 512px chunk) -> 1200, processed by 1184 half-units
#define CH2    150
#define PX2    (KHW / CH2)        // 512
#define NIT2   (KB * CH2)         // 1200
#define NUNITS (GRID * 2)         // 1184

// ---------------- device scratch (zero-init .bss; kernel restores) --------
__device__ float g_sums[KB][KC][KCL];
__device__ float g_cnt[KB][KCL];
__device__ float g_means[KB][KCL][KC];
__device__ float g_inter;
__device__ float g_d2[KB * KCL];
__device__ float g_nk[KB * KCL];
__device__ unsigned int g_q1;        // phase-1 work queue
__device__ unsigned int g_t1[KB];    // per-batch phase-1 done tickets
__device__ unsigned int g_go[KB];    // per-batch means-ready flags
__device__ unsigned int g_q2;        // phase-2 work queue
__device__ unsigned int g_t3;        // phase-2 done ticket (half-units)

#define HBAR(h) asm volatile("bar.sync %0, 128;" :: "r"(1 + (h)) : "memory")

// L2 eviction-priority loads via createpolicy + cache_hint (the form ptxas
// accepts for v4.f32 on sm_103a). Phase 1 pins x in L2 (evict_last);
// phase 2 streams through without displacing the pinned window (evict_first).
__device__ __forceinline__ unsigned long long mkpol_evl() {
    unsigned long long pol;
    asm("createpolicy.fractional.L2::evict_last.b64 %0, 1.0;" : "=l"(pol));
    return pol;
}
__device__ __forceinline__ unsigned long long mkpol_evf() {
    unsigned long long pol;
    asm("createpolicy.fractional.L2::evict_first.b64 %0, 1.0;" : "=l"(pol));
    return pol;
}
__device__ __forceinline__ float4 ldg_pol(const float* p, unsigned long long pol) {
    float4 v;
    asm("ld.global.L2::cache_hint.v4.f32 {%0,%1,%2,%3}, [%4], %5;"
        : "=f"(v.x), "=f"(v.y), "=f"(v.z), "=f"(v.w) : "l"(p), "l"(pol));
    return v;
}

__global__ __launch_bounds__(THR, 4) void fused_loss(const float* __restrict__ x,
                                                     const int* __restrict__ cmask,
                                                     float* __restrict__ out)
{
    __shared__ float2 s_bins[8][KCL * 2 * 32];   // 40960 B (bins / means / msh)
    __shared__ unsigned char s_cm[PX1];
    __shared__ int s_cnt[KCL];
    __shared__ int s_item;
    __shared__ float s_r[8];
    __shared__ unsigned int s_flag;
    __shared__ int s_item2[2];
    __shared__ int s_fin[2];
    __shared__ float s_d2[2][KCL], s_nk[2][KCL];
    __shared__ float s_r1[2][4], s_r2[2][4];

    const int tid  = threadIdx.x;
    const int lane = tid & 31;
    const int warp = tid >> 5;
    float2* wacc2 = s_bins[warp];
    const unsigned long long pol_evl = mkpol_evl();

    // ======================= PHASE 1: cluster sums =======================
    for (;;) {
        if (tid == 0) s_item = (int)atomicAdd(&g_q1, 1u);
        __syncthreads();
        const int item = s_item;
        if (item >= NIT1) break;

        const int b     = item / IT1PB;
        const int r0    = item % IT1PB;
        const int cgrp  = r0 & 1;
        const int pbase = (r0 >> 1) * PX1;

        // zero this warp's bins (warp-private)
#pragma unroll
        for (int i = 0; i < 20; i++) wacc2[i * 32 + lane] = make_float2(0.f, 0.f);
        if (tid < KCL) s_cnt[tid] = 0;

        // stage masks (+ counts only from channel-group 0)
        const int* cmb = cmask + b * KHW + pbase;
        if (cgrp == 0) {
            int cnt[KCL];
#pragma unroll
            for (int k = 0; k < KCL; k++) cnt[k] = 0;
#pragma unroll
            for (int i = 0; i < PX1 / 256; i++) {
                const int p = tid + i * 256;
                const int v = cmb[p];
                s_cm[p] = (unsigned char)v;
#pragma unroll
                for (int k = 0; k < KCL; k++) cnt[k] += (v == k);
            }
            __syncthreads();
#pragma unroll
            for (int k = 0; k < KCL; k++) {
                int v = cnt[k];
#pragma unroll
                for (int o = 16; o; o >>= 1) v += __shfl_xor_sync(0xffffffffu, v, o);
                if (lane == 0) atomicAdd(&s_cnt[k], v);
            }
            __syncthreads();
            if (tid < KCL) atomicAdd(&g_cnt[b][tid], (float)s_cnt[tid]);
        } else {
#pragma unroll
            for (int i = 0; i < PX1 / 256; i++) {
                const int p = tid + i * 256;
                s_cm[p] = (unsigned char)cmb[p];
            }
            __syncthreads();
        }

        // main accumulation: warp owns 4 channels; software-pipelined quads
        const int c0 = cgrp * 32 + warp * 4;
        const float* xp = x + ((size_t)(b * KC + c0)) * KHW + pbase;

#define LOADQ(d0, d1, d2, d3, P)                                   \
        d0 = ldg_pol(xp + (P), pol_evl);                           \
        d1 = ldg_pol(xp + (size_t)KHW + (P), pol_evl);             \
        d2 = ldg_pol(xp + (size_t)2 * KHW + (P), pol_evl);         \
        d3 = ldg_pol(xp + (size_t)3 * KHW + (P), pol_evl)

#define SCATTER_PX(KV, V0, V1, V2, V3) do {                        \
        float2* a = wacc2 + (KV) * 64 + lane;                      \
        float2 t0 = a[0];  t0.x += (V0); t0.y += (V1); a[0]  = t0; \
        float2 t1 = a[32]; t1.x += (V2); t1.y += (V3); a[32] = t1; \
    } while (0)

        float4 c0v, c1v, c2v, c3v;
        unsigned int cmq;
        {
            const int p = 4 * lane;
            LOADQ(c0v, c1v, c2v, c3v, p);
            cmq = *(const unsigned int*)(s_cm + p);
        }
#pragma unroll
        for (int it = 0; it < PX1 / 128; it++) {
            float4 n0, n1, n2, n3;
            unsigned int cmn = 0;
            if (it + 1 < PX1 / 128) {
                const int pn = 4 * lane + (it + 1) * 128;
                LOADQ(n0, n1, n2, n3, pn);
                cmn = *(const unsigned int*)(s_cm + pn);
            }
            SCATTER_PX(cmq & 0xffu,         c0v.x, c1v.x, c2v.x, c3v.x);
            SCATTER_PX((cmq >> 8) & 0xffu,  c0v.y, c1v.y, c2v.y, c3v.y);
            SCATTER_PX((cmq >> 16) & 0xffu, c0v.z, c1v.z, c2v.z, c3v.z);
            SCATTER_PX(cmq >> 24,           c0v.w, c1v.w, c2v.w, c3v.w);
            c0v = n0; c1v = n1; c2v = n2; c3v = n3; cmq = cmn;
        }
#undef LOADQ
#undef SCATTER_PX

        // per-warp bin reduce -> global atomics
#pragma unroll
        for (int r = 0; r < KCL * 2; r++) {
            float2 v = wacc2[r * 32 + lane];
#pragma unroll
            for (int o = 16; o; o >>= 1) {
                v.x += __shfl_xor_sync(0xffffffffu, v.x, o);
                v.y += __shfl_xor_sync(0xffffffffu, v.y, o);
            }
            if (lane == 0) {
                const int k  = r >> 1;
                const int jp = r & 1;
                atomicAdd(&g_sums[b][c0 + 2 * jp][k],     v.x);
                atomicAdd(&g_sums[b][c0 + 2 * jp + 1][k], v.y);
            }
        }

        // ---- per-batch ticket: 120th finisher computes batch-b means ----
        __threadfence();
        __syncthreads();
        if (tid == 0)
            s_flag = (atomicAdd(&g_t1[b], 1u) == IT1PB - 1) ? 1u : 0u;
        __syncthreads();

        if (s_flag) {
            __threadfence();
            float* s_means = (float*)&s_bins[0][0];   // bins dead; 10x65 staging
            for (int row = warp; row < KCL; row += 8) {
                const float cntv = g_cnt[b][row];
                const float m0 = g_sums[b][lane][row]      / (cntv + 1e-10f);
                const float m1 = g_sums[b][lane + 32][row] / (cntv + 1e-10f);
                float sq = m0 * m0 + m1 * m1;
#pragma unroll
                for (int o = 16; o; o >>= 1) sq += __shfl_xor_sync(0xffffffffu, sq, o);
                const float inv = 1.0f / fmaxf(sqrtf(sq), 1e-12f);
                const float n0 = m0 * inv, n1 = m1 * inv;
                g_means[b][row][lane]      = n0;
                g_means[b][row][lane + 32] = n1;
                s_means[row * 65 + lane]      = n0;
                s_means[row * 65 + lane + 32] = n1;
                g_sums[b][lane][row]      = 0.0f;     // reset for next replay
                g_sums[b][lane + 32][row] = 0.0f;
                if (lane == 0) g_cnt[b][row] = 0.0f;
            }
            __syncthreads();

            // inter loss for batch b: 90 ordered pairs / 8 warps
            float acc_inter = 0.f;
            for (int pr = warp; pr < KCL * (KCL - 1); pr += 8) {
                const int k = pr / 9;
                int l = pr % 9; if (l >= k) l++;
                const float* mk = &s_means[k * 65];
                const float* ml = &s_means[l * 65];
                float dv = mk[lane] * ml[lane] + mk[lane + 32] * ml[lane + 32];
#pragma unroll
                for (int o = 16; o; o >>= 1) dv += __shfl_xor_sync(0xffffffffu, dv, o);
                const float h = fmaxf(DELTA_C - 0.5f * (1.0f - dv), 0.0f);
                if (lane == 0) acc_inter += h * h;
            }
            if (lane == 0) s_r[warp] = acc_inter;
            __syncthreads();
            if (tid == 0) {
                float t = 0.f;
#pragma unroll
                for (int w = 0; w < 8; w++) t += s_r[w];
                atomicAdd(&g_inter, t);
                __threadfence();
                atomicExch(&g_go[b], 1u);     // release batch b
            }
            __syncthreads();
        }
    }

    // ======================= PHASE 2: intra pass ==========================
    // two independent 128-thread half-units per block; REVERSE batch order
    // so early items consume the x tail phase-1 just pinned in L2.
    const int half = warp >> 2;
    const int htid = tid & 127;
    const int hwarp = warp & 3;
    float* msh = (float*)&s_bins[0][0] + half * 704;
    int curb = -1;
    const unsigned long long pol_evf = mkpol_evf();

    for (;;) {
        if (htid == 0) s_item2[half] = (int)atomicAdd(&g_q2, 1u);
        HBAR(half);
        const int it2 = s_item2[half];
        if (it2 >= NIT2) break;
        const int rit   = (NIT2 - 1) - it2;       // reversed traversal
        const int b     = rit / CH2;
        const int pbase = (rit % CH2) * PX2;

        if (htid == 0) {
            while (atomicAdd(&g_go[b], 0u) == 0u) __nanosleep(64);
        }
        HBAR(half);
        __threadfence();                           // acquire g_means[b]

        if (b != curb) {
            for (int i = htid; i < KCL * KC; i += 128)
                msh[(i >> 6) * 65 + (i & 63)] = ((const float*)g_means)[b * KCL * KC + i];
            curb = b;
        }
        if (htid < KCL) { s_d2[half][htid] = 0.f; s_nk[half][htid] = 0.f; }
        HBAR(half);

        const int p0 = pbase + htid * 4;
        const int4 cm4 = *(const int4*)(cmask + b * KHW + p0);
        const float* xb = x + (size_t)b * KC * KHW + p0;

        const int kk4[4] = { cm4.x, cm4.y, cm4.z, cm4.w };
        const float* mp0 = &msh[cm4.x * 65];
        const float* mp1 = &msh[cm4.y * 65];
        const float* mp2 = &msh[cm4.z * 65];
        const float* mp3 = &msh[cm4.w * 65];

        float d0 = 0.f, d1 = 0.f, d2 = 0.f, d3 = 0.f;
#pragma unroll
        for (int w = 0; w < KC / 8; w++) {
            float4 buf[8];
#pragma unroll
            for (int cc = 0; cc < 8; cc++)
                buf[cc] = ldg_pol(xb + (size_t)(w * 8 + cc) * KHW, pol_evf);
#pragma unroll
            for (int cc = 0; cc < 8; cc++) {
                const int c = w * 8 + cc;
                d0 = fmaf(buf[cc].x, mp0[c], d0);
                d1 = fmaf(buf[cc].y, mp1[c], d1);
                d2 = fmaf(buf[cc].z, mp2[c], d2);
                d3 = fmaf(buf[cc].w, mp3[c], d3);
            }
        }

        const float dots[4] = { d0, d1, d2, d3 };
#pragma unroll
        for (int i = 0; i < 4; i++) {
            const float dd = 0.5f * (1.0f - dots[i]);
            atomicAdd(&s_d2[half][kk4[i]], dd * dd);
            if (dd > ALPHA_C) atomicAdd(&s_nk[half][kk4[i]], 1.0f);
        }
        HBAR(half);
        if (htid < KCL) {
            atomicAdd(&g_d2[b * KCL + htid], s_d2[half][htid]);
            atomicAdd(&g_nk[b * KCL + htid], s_nk[half][htid]);
        }
    }

    // ---- phase-2 ticket: last half-unit finalizes + resets everything ----
    __threadfence();
    if (htid == 0) s_fin[half] = (atomicAdd(&g_t3, 1u) == NUNITS - 1) ? 1 : 0;
    HBAR(half);
    if (!s_fin[half]) return;
    __threadfence();

    float acc_intra = 0.f, acc_ind = 0.f;
    if (htid < KB * KCL) {
        const float nk = g_nk[htid];
        acc_intra = g_d2[htid] / (fmaxf(nk, MINW_C) * (float)KCL);
        acc_ind   = nk;
        g_nk[htid] = 0.f;
        g_d2[htid] = 0.f;
    }
    float v1 = acc_intra, v2 = acc_ind;
#pragma unroll
    for (int o = 16; o; o >>= 1) {
        v1 += __shfl_xor_sync(0xffffffffu, v1, o);
        v2 += __shfl_xor_sync(0xffffffffu, v2, o);
    }
    if (lane == 0) { s_r1[half][hwarp] = v1; s_r2[half][hwarp] = v2; }
    HBAR(half);
    if (htid == 0) {
        float t1 = 0.f, t2 = 0.f;
#pragma unroll
        for (int w = 0; w < 4; w++) { t1 += s_r1[half][w]; t2 += s_r2[half][w]; }
        const float inter_loss = g_inter / ((float)(KCL * (KCL - 1) / 2) * (float)KB);
        const float intra_loss = (t2 > 0.f) ? (t1 / (float)KB) : 0.f;
        out[0] = intra_loss + inter_loss;
        out[1] = intra_loss;
        out[2] = inter_loss;
        // reset control state for the next graph replay
        g_q1 = 0u; g_q2 = 0u; g_t3 = 0u; g_inter = 0.f;
    }
    if (htid < KB) { g_t1[htid] = 0u; g_go[htid] = 0u; }
}

// =====================================================================
extern "C" void kernel_launch(void* const* d_in, const int* in_sizes, int n_in,
                              void* d_out, int out_size)
{
    const float* x   = (const float*)d_in[0];
    const int*   cm  = (const int*)d_in[1];
    float*       out = (float*)d_out;

    fused_loss<<<GRID, THR>>>(x, cm, out);
}